// round 3
// baseline (speedup 1.0000x reference)
#include <cuda_runtime.h>
#include <cstdint>
#include <cstddef>

// ---------------------------------------------------------------------------
// Lfm2ShortConv (sm_103 legacy-tensor path; tcgen05 unavailable in this build).
//   BCx = hidden @ W_in^T        GEMM1  8192x6144x2048
//   y   = C * conv3(B*x)         fused elementwise
//   out = y @ W_out^T            GEMM2  8192x2048x2048
// TF32 mma.sync.m16n8k8, fp32 accum. Inputs pre-rounded to tf32 AND stored
// with per-32-block k-permutation k' = (k&3)*8 + (k>>2) so that each MMA
// thread's fragment elements are contiguous -> LDS.128 fragment loads.
// ---------------------------------------------------------------------------

#define SEQ  4096
#define HD   2048
#define MTOT 8192
#define KD   2048
#define NN1  6144
#define NN2  2048

// Scratch (__device__ globals: allocation-free rule)
__device__ float g_hid [(size_t)MTOT * KD];   // rounded+permuted hidden
__device__ float g_win [(size_t)NN1  * KD];   // rounded+permuted W_in
__device__ float g_wout[(size_t)NN2  * KD];   // rounded+permuted W_out
__device__ float g_BCx [(size_t)MTOT * NN1];  // GEMM1 out (fp32, plain layout)
__device__ float g_y   [(size_t)MTOT * KD];   // conv out (rounded+permuted)

// ---- GEMM tiling ----------------------------------------------------------
constexpr int BM = 128, BN = 128, BK = 32;
constexpr int NTHREADS = 256;                 // 8 warps: 2 (M) x 4 (N)
constexpr int WM_ = 64, WN_ = 32;
constexpr int MT = WM_ / 16;                  // 4
constexpr int NT = WN_ / 8;                   // 4
constexpr int ASTRIDE = BK + 4;               // 36 floats: LDS.128 conflict-free
constexpr int TILE_FLOATS = BM * ASTRIDE;     // per operand per stage
constexpr int SMEM_FLOATS = 4 * TILE_FLOATS;  // 2 stages x (A+B)
constexpr int SMEM_BYTES  = SMEM_FLOATS * 4;  // 73728

// ---- PTX helpers ----------------------------------------------------------
__device__ __forceinline__ void cp_async16(void* smem_dst, const void* gsrc) {
    uint32_t saddr = (uint32_t)__cvta_generic_to_shared(smem_dst);
    asm volatile("cp.async.cg.shared.global [%0], [%1], 16;\n"
                 :: "r"(saddr), "l"(gsrc));
}
__device__ __forceinline__ void cp_commit() {
    asm volatile("cp.async.commit_group;\n");
}
template <int N>
__device__ __forceinline__ void cp_wait() {
    asm volatile("cp.async.wait_group %0;\n" :: "n"(N));
}
__device__ __forceinline__ uint32_t f2tf(float f) {
    uint32_t u;
    asm("cvt.rna.tf32.f32 %0, %1;" : "=r"(u) : "f"(f));
    return u;
}
__device__ __forceinline__ void mma_tf32(float* c, const uint32_t* a, const uint32_t* b) {
    asm volatile(
        "mma.sync.aligned.m16n8k8.row.col.f32.tf32.tf32.f32 "
        "{%0,%1,%2,%3}, {%4,%5,%6,%7}, {%8,%9}, {%0,%1,%2,%3};\n"
        : "+f"(c[0]), "+f"(c[1]), "+f"(c[2]), "+f"(c[3])
        : "r"(a[0]), "r"(a[1]), "r"(a[2]), "r"(a[3]), "r"(b[0]), "r"(b[1]));
}

// ---- TN GEMM: C[M,N] = A[M,K] * B[N,K]^T  (k-permuted tf32 operands) ------
__global__ void __launch_bounds__(NTHREADS, 2)
gemm_tf32_tn(const float* __restrict__ A, const float* __restrict__ B,
             float* __restrict__ C, int N, int K)
{
    extern __shared__ float sm[];
    float* As = sm;                       // [2][BM][ASTRIDE]
    float* Bs = sm + 2 * TILE_FLOATS;     // [2][BN][ASTRIDE]

    const int tid  = threadIdx.x;
    const int lane = tid & 31;
    const int warp = tid >> 5;
    const int wm = (warp >> 2) * WM_;     // 0 or 64
    const int wn = (warp & 3)  * WN_;     // 0,32,64,96
    const int g  = lane >> 2;             // groupID (0..7)
    const int c  = lane & 3;              // thread-in-group

    const int brow = blockIdx.y * BM;
    const int bcol = blockIdx.x * BN;
    const float* Ag = A + (size_t)brow * K;
    const float* Bg = B + (size_t)bcol * K;

    float acc[MT][NT][4];
    #pragma unroll
    for (int i = 0; i < MT; i++)
        #pragma unroll
        for (int j = 0; j < NT; j++)
            #pragma unroll
            for (int q = 0; q < 4; q++) acc[i][j][q] = 0.f;

    const int KT = K / BK;

    auto prefetch = [&](int kt, int st) {
        const int k0 = kt * BK;
        #pragma unroll
        for (int i = 0; i < 4; i++) {                     // A tile: 128x32
            int idx = tid + i * NTHREADS;
            int r  = idx >> 3;
            int cc = (idx & 7) << 2;
            cp_async16(&As[st * TILE_FLOATS + r * ASTRIDE + cc],
                       Ag + (size_t)r * K + k0 + cc);
        }
        #pragma unroll
        for (int i = 0; i < 4; i++) {                     // B tile: 128x32
            int idx = tid + i * NTHREADS;
            int r  = idx >> 3;
            int cc = (idx & 7) << 2;
            cp_async16(&Bs[st * TILE_FLOATS + r * ASTRIDE + cc],
                       Bg + (size_t)r * K + k0 + cc);
        }
        cp_commit();
    };

    prefetch(0, 0);

    for (int kt = 0; kt < KT; ++kt) {
        const int st = kt & 1;
        if (kt + 1 < KT) { prefetch(kt + 1, st ^ 1); cp_wait<1>(); }
        else             { cp_wait<0>(); }
        __syncthreads();

        const float* as = &As[st * TILE_FLOATS];
        const float* bs = &Bs[st * TILE_FLOATS];

        // permuted layout: thread c's smem cols [c*8 .. c*8+7] hold original
        // k = c, c+4, c+8, ..., c+28.  half h covers ks = 2h, 2h+1.
        #pragma unroll
        for (int h = 0; h < 2; ++h) {
            float4 bf[NT];
            #pragma unroll
            for (int ni = 0; ni < NT; ++ni)
                bf[ni] = *(const float4*)(bs + (wn + ni * 8 + g) * ASTRIDE + c * 8 + h * 4);

            #pragma unroll
            for (int mi = 0; mi < MT; ++mi) {
                const int r0 = wm + mi * 16 + g;
                float4 a_lo = *(const float4*)(as + r0 * ASTRIDE + c * 8 + h * 4);
                float4 a_hi = *(const float4*)(as + (r0 + 8) * ASTRIDE + c * 8 + h * 4);
                const float* alo = &a_lo.x;
                const float* ahi = &a_hi.x;

                #pragma unroll
                for (int k2 = 0; k2 < 2; ++k2) {          // ks = 2h + k2
                    uint32_t af[4];
                    af[0] = __float_as_uint(alo[2 * k2 + 0]);   // (g,   ks*8+c)
                    af[1] = __float_as_uint(ahi[2 * k2 + 0]);   // (g+8, ks*8+c)
                    af[2] = __float_as_uint(alo[2 * k2 + 1]);   // (g,   ks*8+c+4)
                    af[3] = __float_as_uint(ahi[2 * k2 + 1]);   // (g+8, ks*8+c+4)
                    #pragma unroll
                    for (int ni = 0; ni < NT; ++ni) {
                        const float* bp = &bf[ni].x;
                        uint32_t bfr[2];
                        bfr[0] = __float_as_uint(bp[2 * k2 + 0]);
                        bfr[1] = __float_as_uint(bp[2 * k2 + 1]);
                        mma_tf32(acc[mi][ni], af, bfr);
                    }
                }
            }
        }
        __syncthreads();
    }

    // Epilogue: C frag c0=(g,2c) c1=(g,2c+1) c2=(g+8,2c) c3=(g+8,2c+1)
    #pragma unroll
    for (int mi = 0; mi < MT; ++mi) {
        const int r0 = brow + wm + mi * 16 + g;
        #pragma unroll
        for (int ni = 0; ni < NT; ++ni) {
            const int cc = bcol + wn + ni * 8 + 2 * c;
            *reinterpret_cast<float2*>(C + (size_t)r0 * N + cc) =
                make_float2(acc[mi][ni][0], acc[mi][ni][1]);
            *reinterpret_cast<float2*>(C + (size_t)(r0 + 8) * N + cc) =
                make_float2(acc[mi][ni][2], acc[mi][ni][3]);
        }
    }
}

// ---- round to tf32 (RNA) + per-32-block k-permutation ---------------------
// out[blk*32 + (t*8 + j/4)] = rna(in[blk*32 + j + t]),  j = 4-aligned, t=0..3
__global__ void __launch_bounds__(256)
round_perm_k(const float4* __restrict__ in, float* __restrict__ out, int n4)
{
    for (int i = blockIdx.x * blockDim.x + threadIdx.x; i < n4; i += gridDim.x * blockDim.x) {
        float4 v = in[i];
        int e = i * 4;
        int base = (e & ~31) + ((e & 31) >> 2);
        out[base +  0] = __uint_as_float(f2tf(v.x));
        out[base +  8] = __uint_as_float(f2tf(v.y));
        out[base + 16] = __uint_as_float(f2tf(v.z));
        out[base + 24] = __uint_as_float(f2tf(v.w));
    }
}

// ---- conv + gating; output rounded to tf32 and k-permuted (feeds GEMM2 A) -
__global__ void __launch_bounds__(256)
conv_gate_kernel(const float* __restrict__ BCx, const float* __restrict__ w,
                 float* __restrict__ y)
{
    const int idx = blockIdx.x * blockDim.x + threadIdx.x;   // < 8192*2048
    const int h = idx & (HD - 1);
    const int m = idx >> 11;
    const int s = m & (SEQ - 1);

    const float* row = BCx + (size_t)m * NN1;
    const float w0 = w[h * 3 + 0];
    const float w1 = w[h * 3 + 1];
    const float w2 = w[h * 3 + 2];

    float acc = w2 * (row[h] * row[2 * HD + h]);
    if (s >= 1) { const float* r1 = row - NN1;     acc += w1 * (r1[h] * r1[2 * HD + h]); }
    if (s >= 2) { const float* r2 = row - 2 * NN1; acc += w0 * (r2[h] * r2[2 * HD + h]); }
    const float val = acc * row[HD + h];

    const int j = h & 31;
    const int hp = (h & ~31) + ((j & 3) << 3) + (j >> 2);    // permuted col
    y[(size_t)m * HD + hp] = __uint_as_float(f2tf(val));
}

// ---------------------------------------------------------------------------
extern "C" void kernel_launch(void* const* d_in, const int* in_sizes, int n_in,
                              void* d_out, int out_size)
{
    const float* hs    = (const float*)d_in[0];   // [2,4096,2048]
    const float* Win   = (const float*)d_in[1];   // [6144,2048]
    const float* convw = (const float*)d_in[2];   // [2048,1,3]
    const float* Wout  = (const float*)d_in[3];   // [2048,2048]
    float* out = (float*)d_out;

    float *hid_r, *win_r, *wout_r, *bcx, *y;
    cudaGetSymbolAddress((void**)&hid_r,  g_hid);
    cudaGetSymbolAddress((void**)&win_r,  g_win);
    cudaGetSymbolAddress((void**)&wout_r, g_wout);
    cudaGetSymbolAddress((void**)&bcx,    g_BCx);
    cudaGetSymbolAddress((void**)&y,      g_y);

    cudaFuncSetAttribute(gemm_tf32_tn,
                         cudaFuncAttributeMaxDynamicSharedMemorySize, SMEM_BYTES);

    // pre-round to tf32 + k-permute GEMM operands
    round_perm_k<<<2048, 256>>>((const float4*)hs,   hid_r,  MTOT * KD / 4);
    round_perm_k<<<2048, 256>>>((const float4*)Win,  win_r,  NN1  * KD / 4);
    round_perm_k<<<2048, 256>>>((const float4*)Wout, wout_r, NN2  * KD / 4);

    // GEMM1: BCx = hidden @ W_in^T   [8192 x 6144]
    gemm_tf32_tn<<<dim3(NN1 / BN, MTOT / BM), NTHREADS, SMEM_BYTES>>>(
        hid_r, win_r, bcx, NN1, KD);

    // conv + gating -> y [8192 x 2048] (rounded + permuted)
    conv_gate_kernel<<<(MTOT * HD) / 256, 256>>>(bcx, convw, y);

    // GEMM2: out = y @ W_out^T   [8192 x 2048]
    gemm_tf32_tn<<<dim3(NN2 / BN, MTOT / BM), NTHREADS, SMEM_BYTES>>>(
        y, wout_r, out, NN2, KD);
}